// round 14
// baseline (speedup 1.0000x reference)
#include <cuda_runtime.h>
#include <cuda_fp16.h>
#include <cstdint>

#define NUM_LEVELS 16
#define BASE_RES   16
#define TABLE_MASK ((1u << 19) - 1u)
#define P1 2654435761u
#define P2 805459861u

#define FP16_SCALE    8192.0f          // 2^13, exact
#define FP16_INVSCALE 1.220703125e-4f  // 2^-13, exact

// ---- dense quad records for levels 0..2 ----
#define Q0_SIZE (17 * 16 * 16)
#define Q1_SIZE (33 * 32 * 32)
#define Q2_SIZE (65 * 64 * 64)
#define Q1_BASE Q0_SIZE
#define Q2_BASE (Q0_SIZE + Q1_SIZE)
#define Q_TOTAL (Q0_SIZE + Q1_SIZE + Q2_SIZE)   // 304384 (~4.9 MB)

__device__ uint4 g_quad[Q_TOTAL];

// fp16 hashed-level tables (levels 3..15) (~27.3 MB)
#define NUM_HASHED 13
#define HTAB_ENTRIES (NUM_HASHED << 19)
__device__ uint32_t g_htab[HTAB_ENTRIES];

// packed points (~8.4 MB)
#define N_MAX 524288
__device__ float4 g_xpack[N_MAX];

// ---- work queue / flags ----
// flag index: 0 = xpack, 1 = quad, 2+j = hashed level j (j = l-3)
#define NFLAGS 15
__device__ int g_item_ctr;
__device__ int g_chunk_ctr;
__device__ int g_done[NFLAGS];
__device__ volatile int g_flag[NFLAGS];

#define CONV_ITEMS_PER_LVL 128              // 2^19 entries / 4096
#define CONV_ITEMS (NUM_HASHED * CONV_ITEMS_PER_LVL)   // 1664
#define QUAD_ITEMS ((Q_TOTAL + 4095) / 4096)           // 75

__device__ __forceinline__ uint32_t pack_h2(float a, float b)
{
    half2 h = __floats2half2_rn(a * FP16_SCALE, b * FP16_SCALE);
    return *reinterpret_cast<uint32_t*>(&h);
}

__device__ __forceinline__ float2 unpack_h2(uint32_t u)
{
    half2 h = *reinterpret_cast<half2*>(&u);
    return __half22float2(h);
}

__global__ void reset_kernel()
{
    int t = threadIdx.x;
    if (t == 0) { g_item_ctr = 0; g_chunk_ctr = 0; }
    if (t < NFLAGS) { g_done[t] = 0; g_flag[t] = 0; }
}

__global__ __launch_bounds__(256)
void fused_kernel(const float* __restrict__ tables,
                  const float* __restrict__ x,
                  float* __restrict__ out,
                  int N, int xpk_items, int total_items, int nchunks)
{
    __shared__ int s_it;
    __shared__ float2 stage[256 * 17];   // padded: row stride 17 float2 (136B)

    const int tid = threadIdx.x;

    // ================= Phase 1: drain prepass work queue =================
    while (true) {
        if (tid == 0) s_it = atomicAdd(&g_item_ctr, 1);
        __syncthreads();
        int it = s_it;
        if (it >= total_items) break;

        int fi;  // flag index to credit
        if (it < xpk_items) {
            // ---- xpack item: 4096 points ----
            int base = it * 4096;
#pragma unroll
            for (int k = 0; k < 16; ++k) {
                int n = base + k * 256 + tid;
                if (n < N) {
                    float4 p;
                    p.x = __ldg(x + 3 * n + 0);
                    p.y = __ldg(x + 3 * n + 1);
                    p.z = __ldg(x + 3 * n + 2);
                    p.w = 0.0f;
                    g_xpack[n] = p;
                }
            }
            fi = 0;
        } else if (it < xpk_items + CONV_ITEMS) {
            // ---- convert item: 4096 entries of hashed level j ----
            int slab = it - xpk_items;
            int j = slab >> 7;           // level index 0..12
            int s = slab & 127;
            int g4base = (j << 17) + s * 1024 + tid;   // uint4 index
            const float4* __restrict__ src = (const float4*)tables + (3 << 18);
#pragma unroll
            for (int k = 0; k < 4; ++k) {
                int g4 = g4base + k * 256;
                float4 v0 = __ldg(src + 2 * g4);
                float4 v1 = __ldg(src + 2 * g4 + 1);
                uint4 o;
                o.x = pack_h2(v0.x, v0.y);
                o.y = pack_h2(v0.z, v0.w);
                o.z = pack_h2(v1.x, v1.y);
                o.w = pack_h2(v1.z, v1.w);
                ((uint4*)g_htab)[g4] = o;
            }
            fi = 2 + j;
        } else {
            // ---- quad item: 4096 records ----
            int qslab = it - xpk_items - CONV_ITEMS;
            int base = qslab * 4096;
#pragma unroll 1
            for (int k = 0; k < 16; ++k) {
                int t = base + k * 256 + tid;
                if (t >= Q_TOTAL) break;

                int l, rem, R;
                if (t < Q1_BASE)      { l = 0; rem = t;           R = 16; }
                else if (t < Q2_BASE) { l = 1; rem = t - Q1_BASE; R = 32; }
                else                  { l = 2; rem = t - Q2_BASE; R = 64; }

                int z = rem % R;
                int y = (rem / R) % R;
                int xg = rem / (R * R);

                uint32_t hx  = (uint32_t)xg ^ (uint32_t)l;
                uint32_t hy0 = (uint32_t)y * P1;
                uint32_t hy1 = hy0 + P1;
                uint32_t hz0 = (uint32_t)z * P2;
                uint32_t hz1 = hz0 + P2;

                const float2* __restrict__ tbl = (const float2*)tables + ((size_t)l << 19);
                float2 e00 = __ldg(tbl + ((hx ^ hy0 ^ hz0) & TABLE_MASK));
                float2 e01 = __ldg(tbl + ((hx ^ hy0 ^ hz1) & TABLE_MASK));
                float2 e10 = __ldg(tbl + ((hx ^ hy1 ^ hz0) & TABLE_MASK));
                float2 e11 = __ldg(tbl + ((hx ^ hy1 ^ hz1) & TABLE_MASK));

                uint4 o;
                o.x = pack_h2(e00.x, e00.y);
                o.y = pack_h2(e01.x, e01.y);
                o.z = pack_h2(e10.x, e10.y);
                o.w = pack_h2(e11.x, e11.y);
                g_quad[t] = o;
            }
            fi = 1;
        }

        __threadfence();          // release: our stores visible GPU-wide
        __syncthreads();          // all threads done + fenced before credit
        if (tid == 0) {
            int target = (fi == 0) ? xpk_items
                       : (fi == 1) ? QUAD_ITEMS
                                   : CONV_ITEMS_PER_LVL;
            int d = atomicAdd(&g_done[fi], 1) + 1;
            if (d == target) g_flag[fi] = 1;
        }
    }

    // ================= Phase 2: main encode, chunk-stealing =================
    unsigned ready = 0;

    while (true) {
        if (tid == 0) s_it = atomicAdd(&g_chunk_ctr, 1);
        __syncthreads();
        int c = s_it;
        if (c >= nchunks) break;

        // wait for xpack
        if (!((ready >> 0) & 1u)) {
            if (tid == 0) { while (g_flag[0] == 0) __nanosleep(128); }
            __syncthreads();
            __threadfence();      // acquire
            ready |= 1u;
        }

        int n = c * 256 + tid;
        bool valid = (n < N);
        float4 p = valid ? __ldg(g_xpack + n) : make_float4(0.f, 0.f, 0.f, 0.f);

        const float HI = 0.999999f;
        float xn = fminf(fmaxf((p.x + 1.0f) * 0.5f, 0.0f), HI);
        float yn = fminf(fmaxf((p.y + 1.0f) * 0.5f, 0.0f), HI);
        float zn = fminf(fmaxf((p.z + 1.0f) * 0.5f, 0.0f), HI);

        // process hashed levels 3..15 first (pipelined), dense 0..2 last
#pragma unroll 1
        for (int i = 0; i < 16; ++i) {
            int l = (i < 13) ? (i + 3) : (i - 13);
            int fi = (i < 13) ? (2 + i) : 1;

            if (!((ready >> fi) & 1u)) {
                if (tid == 0) { while (g_flag[fi] == 0) __nanosleep(128); }
                __syncthreads();
                __threadfence();  // acquire
                ready |= 1u << fi;
            }

            float res = (float)(BASE_RES << l);
            float sx = xn * res, sy = yn * res, sz = zn * res;
            float fx0 = floorf(sx), fy0 = floorf(sy), fz0 = floorf(sz);
            float fx = sx - fx0, fy = sy - fy0, fz = sz - fz0;
            int cx = (int)fx0, cy = (int)fy0, cz = (int)fz0;

            float wx1 = fx, wx0 = 1.0f - fx;
            float wy1 = fy, wy0 = 1.0f - fy;
            float wz1 = fz, wz0 = 1.0f - fz;

            float a0, a1;

            if (i >= 13) {
                // ---- dense path ----
                int R = BASE_RES << l;
                int base = (l == 0) ? 0 : (l == 1) ? Q1_BASE : Q2_BASE;
                int r0 = base + (cx * R + cy) * R + cz;
                int r1 = r0 + R * R;

                uint4 q0 = __ldg(g_quad + r0);
                uint4 q1 = __ldg(g_quad + r1);

                float2 e;
                float w;
                w = wx0 * wy0 * wz0; e = unpack_h2(q0.x); a0 = w * e.x;          a1 = w * e.y;
                w = wx0 * wy0 * wz1; e = unpack_h2(q0.y); a0 = fmaf(w, e.x, a0); a1 = fmaf(w, e.y, a1);
                w = wx0 * wy1 * wz0; e = unpack_h2(q0.z); a0 = fmaf(w, e.x, a0); a1 = fmaf(w, e.y, a1);
                w = wx0 * wy1 * wz1; e = unpack_h2(q0.w); a0 = fmaf(w, e.x, a0); a1 = fmaf(w, e.y, a1);
                w = wx1 * wy0 * wz0; e = unpack_h2(q1.x); a0 = fmaf(w, e.x, a0); a1 = fmaf(w, e.y, a1);
                w = wx1 * wy0 * wz1; e = unpack_h2(q1.y); a0 = fmaf(w, e.x, a0); a1 = fmaf(w, e.y, a1);
                w = wx1 * wy1 * wz0; e = unpack_h2(q1.z); a0 = fmaf(w, e.x, a0); a1 = fmaf(w, e.y, a1);
                w = wx1 * wy1 * wz1; e = unpack_h2(q1.w); a0 = fmaf(w, e.x, a0); a1 = fmaf(w, e.y, a1);
            } else {
                // ---- hashed path ----
                uint32_t hx0 = (uint32_t)cx;
                uint32_t hx1 = hx0 + 1u;
                uint32_t hy0 = (uint32_t)cy * P1;
                uint32_t hy1 = hy0 + P1;
                uint32_t hzb = (uint32_t)cz * P2;
                uint32_t hz0 = hzb        ^ (uint32_t)l;
                uint32_t hz1 = (hzb + P2) ^ (uint32_t)l;

                const uint32_t* __restrict__ tbl = g_htab + ((size_t)i << 19);

                uint32_t hj[4];
                hj[0] = hy0 ^ hz0;
                hj[1] = hy0 ^ hz1;
                hj[2] = hy1 ^ hz0;
                hj[3] = hy1 ^ hz1;

                uint32_t t = hx0 ^ hx1;
                float2 e[8];

                if (t == 1u) {
                    const uint2* __restrict__ tbl2 = (const uint2*)tbl;
#pragma unroll
                    for (int j = 0; j < 4; ++j) {
                        uint32_t i0 = (hx0 ^ hj[j]) & TABLE_MASK;
                        uint2 q = __ldg(tbl2 + (i0 >> 1));
                        uint32_t a = i0 & 1u;
                        e[j]     = unpack_h2(a ? q.y : q.x);
                        e[j + 4] = unpack_h2(a ? q.x : q.y);
                    }
                } else if (t == 3u) {
                    const uint4* __restrict__ tbl4 = (const uint4*)tbl;
#pragma unroll
                    for (int j = 0; j < 4; ++j) {
                        uint32_t i0 = (hx0 ^ hj[j]) & TABLE_MASK;
                        uint4 q = __ldg(tbl4 + (i0 >> 2));
                        uint32_t a = i0 & 3u;
                        uint32_t ea = (a & 2u) ? ((a & 1u) ? q.w : q.z)
                                               : ((a & 1u) ? q.y : q.x);
                        uint32_t eb = (a & 2u) ? ((a & 1u) ? q.x : q.y)
                                               : ((a & 1u) ? q.z : q.w);
                        e[j]     = unpack_h2(ea);
                        e[j + 4] = unpack_h2(eb);
                    }
                } else {
#pragma unroll
                    for (int j = 0; j < 4; ++j) {
                        e[j]     = unpack_h2(__ldg(tbl + ((hx0 ^ hj[j]) & TABLE_MASK)));
                        e[j + 4] = unpack_h2(__ldg(tbl + ((hx1 ^ hj[j]) & TABLE_MASK)));
                    }
                }

                float w[8];
#pragma unroll
                for (int k = 0; k < 8; ++k) {
                    w[k] = ((k & 4) ? wx1 : wx0)
                         * ((k & 2) ? wy1 : wy0)
                         * ((k & 1) ? wz1 : wz0);
                }
                a0 = 0.0f; a1 = 0.0f;
#pragma unroll
                for (int k = 0; k < 8; ++k) {
                    a0 = fmaf(w[k], e[k].x, a0);
                    a1 = fmaf(w[k], e[k].y, a1);
                }
            }

            stage[tid * 17 + l] = make_float2(a0 * FP16_INVSCALE, a1 * FP16_INVSCALE);
        }

        __syncthreads();

        // coalesced flush: 256 points x 128B, float4-wide
        float4* out4 = (float4*)out;
        int nf4 = N << 3;   // total float4s
#pragma unroll
        for (int k = 0; k < 8; ++k) {
            int f4i = tid + k * 256;
            int pl = f4i >> 3;
            int q  = f4i & 7;
            float2 a = stage[pl * 17 + 2 * q];
            float2 b = stage[pl * 17 + 2 * q + 1];
            int G = c * 2048 + f4i;
            if (G < nf4) out4[G] = make_float4(a.x, a.y, b.x, b.y);
        }
        __syncthreads();   // protect stage + s_it for next chunk
    }
}

extern "C" void kernel_launch(void* const* d_in, const int* in_sizes, int n_in,
                              void* d_out, int out_size)
{
    const float* x      = (const float*)d_in[0];
    const float* tables = (const float*)d_in[1];
    float* out          = (float*)d_out;

    int N = in_sizes[0] / 3;
    int xpk_items = (N + 4095) / 4096;
    int total_items = xpk_items + CONV_ITEMS + QUAD_ITEMS;
    int nchunks = (N + 255) / 256;

    reset_kernel<<<1, 32>>>();
    fused_kernel<<<nchunks, 256>>>(tables, x, out, N, xpk_items, total_items, nchunks);
}

// round 16
// speedup vs baseline: 1.2513x; 1.2513x over previous
#include <cuda_runtime.h>
#include <cuda_fp16.h>
#include <cstdint>

#define NUM_LEVELS 16
#define BASE_RES   16
#define TABLE_MASK ((1u << 19) - 1u)
#define P1 2654435761u
#define P2 805459861u

#define FP16_SCALE    8192.0f          // 2^13, exact
#define FP16_INVSCALE 1.220703125e-4f  // 2^-13, exact

// ---- dense quad records for levels 0..2 ----
#define Q0_SIZE (17 * 16 * 16)
#define Q1_SIZE (33 * 32 * 32)
#define Q2_SIZE (65 * 64 * 64)
#define Q1_BASE Q0_SIZE
#define Q2_BASE (Q0_SIZE + Q1_SIZE)
#define Q_TOTAL (Q0_SIZE + Q1_SIZE + Q2_SIZE)   // 304384 (~4.9 MB)

__device__ uint4 g_quad[Q_TOTAL];

// fp16 hashed-level tables (levels 3..15) (~27.3 MB)
#define NUM_HASHED 13
#define HTAB_ENTRIES (NUM_HASHED << 19)
__device__ uint32_t g_htab[HTAB_ENTRIES];

// ---- work queue / flags ----
// flag 0 = quad (levels 0..2); flag 1+j = hashed level j (= level 3+j)
#define NFLAGS 14
#define QUAD_ITEMS ((Q_TOTAL + 4095) / 4096)            // 75
#define CONV_ITEMS_PER_LVL 128                          // 2^19 / 4096
#define CONV_ITEMS (NUM_HASHED * CONV_ITEMS_PER_LVL)    // 1664
#define TOTAL_ITEMS (QUAD_ITEMS + CONV_ITEMS)           // 1739

__device__ int g_item_ctr;
__device__ int g_done[NFLAGS];
__device__ volatile int g_flag[NFLAGS];

__device__ __forceinline__ uint32_t pack_h2(float a, float b)
{
    half2 h = __floats2half2_rn(a * FP16_SCALE, b * FP16_SCALE);
    return *reinterpret_cast<uint32_t*>(&h);
}

__device__ __forceinline__ float2 unpack_h2(uint32_t u)
{
    half2 h = *reinterpret_cast<half2*>(&u);
    return __half22float2(h);
}

__global__ void reset_kernel()
{
    int t = threadIdx.x;
    if (t == 0) g_item_ctr = 0;
    if (t < NFLAGS) { g_done[t] = 0; g_flag[t] = 0; }
}

__global__ __launch_bounds__(256)
void fused_kernel(const float* __restrict__ tables,
                  const float* __restrict__ x,
                  float* __restrict__ out, int N)
{
    __shared__ int s_it;
    __shared__ float s_x[48];            // 16 points x 3 coords
    __shared__ float2 s_stage[16 * 17];  // [pt][lvl], padded row stride 17

    const int tid = threadIdx.x;

    // ================= Phase 1: drain prepass queue (wave-1 blocks) ========
    for (;;) {
        if (tid == 0) s_it = atomicAdd(&g_item_ctr, 1);
        __syncthreads();
        int it = s_it;
        if (it >= TOTAL_ITEMS) break;

        int fi, target;
        if (it < QUAD_ITEMS) {
            // ---- quad item: up to 4096 dense records ----
            int base = it * 4096;
#pragma unroll 1
            for (int k = 0; k < 16; ++k) {
                int t = base + k * 256 + tid;
                if (t >= Q_TOTAL) break;

                int l, rem, R;
                if (t < Q1_BASE)      { l = 0; rem = t;           R = 16; }
                else if (t < Q2_BASE) { l = 1; rem = t - Q1_BASE; R = 32; }
                else                  { l = 2; rem = t - Q2_BASE; R = 64; }

                int z = rem % R;
                int y = (rem / R) % R;
                int xg = rem / (R * R);

                uint32_t hx  = (uint32_t)xg ^ (uint32_t)l;
                uint32_t hy0 = (uint32_t)y * P1;
                uint32_t hy1 = hy0 + P1;
                uint32_t hz0 = (uint32_t)z * P2;
                uint32_t hz1 = hz0 + P2;

                const float2* __restrict__ tbl = (const float2*)tables + ((size_t)l << 19);
                float2 e00 = __ldg(tbl + ((hx ^ hy0 ^ hz0) & TABLE_MASK));
                float2 e01 = __ldg(tbl + ((hx ^ hy0 ^ hz1) & TABLE_MASK));
                float2 e10 = __ldg(tbl + ((hx ^ hy1 ^ hz0) & TABLE_MASK));
                float2 e11 = __ldg(tbl + ((hx ^ hy1 ^ hz1) & TABLE_MASK));

                uint4 o;
                o.x = pack_h2(e00.x, e00.y);
                o.y = pack_h2(e01.x, e01.y);
                o.z = pack_h2(e10.x, e10.y);
                o.w = pack_h2(e11.x, e11.y);
                g_quad[t] = o;
            }
            fi = 0; target = QUAD_ITEMS;
        } else {
            // ---- convert item: 4096 entries of hashed level j ----
            int slab = it - QUAD_ITEMS;
            int j = slab >> 7;
            int s = slab & 127;
            const float4* __restrict__ src = (const float4*)tables + (3 << 18);
            int g4base = (j << 17) + s * 1024 + tid;
#pragma unroll
            for (int k = 0; k < 4; ++k) {
                int g4 = g4base + k * 256;
                float4 v0 = __ldg(src + 2 * g4);
                float4 v1 = __ldg(src + 2 * g4 + 1);
                uint4 o;
                o.x = pack_h2(v0.x, v0.y);
                o.y = pack_h2(v0.z, v0.w);
                o.z = pack_h2(v1.x, v1.y);
                o.w = pack_h2(v1.z, v1.w);
                ((uint4*)g_htab)[g4] = o;
            }
            fi = 1 + j; target = CONV_ITEMS_PER_LVL;
        }

        __threadfence();          // release our stores
        __syncthreads();          // whole block done + fenced
        if (tid == 0) {
            if (atomicAdd(&g_done[fi], 1) + 1 == target) g_flag[fi] = 1;
        }
        __syncthreads();          // s_it protected for next iteration
    }

    // ================= Phase 2: main encode (original straight-line shape) =
    // warp wp: 16 points x levels {2wp, 2wp+1}; lane -> pt = lane>>1, lvl parity
    {
        int base = blockIdx.x * 48;
        if (tid < 48) {
            int gi = base + tid;
            s_x[tid] = (gi < 3 * N) ? __ldg(x + gi) : 0.0f;
        }
    }
    __syncthreads();

    const int wp   = tid >> 5;
    const int lane = tid & 31;
    const int pt   = lane >> 1;
    const int lvl  = 2 * wp + (lane & 1);
    const int fi   = (lvl < 3) ? 0 : (lvl - 2);

    if (g_flag[fi] == 0) {
        while (g_flag[fi] == 0) __nanosleep(128);
    }
    __threadfence();              // acquire

    float px = s_x[pt * 3 + 0];
    float py = s_x[pt * 3 + 1];
    float pz = s_x[pt * 3 + 2];

    const float HI = 0.999999f;
    float xn = fminf(fmaxf((px + 1.0f) * 0.5f, 0.0f), HI);
    float yn = fminf(fmaxf((py + 1.0f) * 0.5f, 0.0f), HI);
    float zn = fminf(fmaxf((pz + 1.0f) * 0.5f, 0.0f), HI);

    float res = (float)(BASE_RES << lvl);

    float sx = xn * res, sy = yn * res, sz = zn * res;
    float fx0 = floorf(sx), fy0 = floorf(sy), fz0 = floorf(sz);
    float fx = sx - fx0, fy = sy - fy0, fz = sz - fz0;

    int cx = (int)fx0, cy = (int)fy0, cz = (int)fz0;

    float wx1 = fx, wx0 = 1.0f - fx;
    float wy1 = fy, wy0 = 1.0f - fy;
    float wz1 = fz, wz0 = 1.0f - fz;

    float a0, a1;

    if (lvl < 3) {
        // ---- dense path: 2 aligned 16B quad loads ----
        int R = BASE_RES << lvl;
        int qb = (lvl == 0) ? 0 : (lvl == 1) ? Q1_BASE : Q2_BASE;

        int r0 = qb + (cx * R + cy) * R + cz;
        int r1 = r0 + R * R;

        uint4 q0 = __ldg(g_quad + r0);
        uint4 q1 = __ldg(g_quad + r1);

        float2 e;
        float w;
        w = wx0 * wy0 * wz0; e = unpack_h2(q0.x); a0 = w * e.x;          a1 = w * e.y;
        w = wx0 * wy0 * wz1; e = unpack_h2(q0.y); a0 = fmaf(w, e.x, a0); a1 = fmaf(w, e.y, a1);
        w = wx0 * wy1 * wz0; e = unpack_h2(q0.z); a0 = fmaf(w, e.x, a0); a1 = fmaf(w, e.y, a1);
        w = wx0 * wy1 * wz1; e = unpack_h2(q0.w); a0 = fmaf(w, e.x, a0); a1 = fmaf(w, e.y, a1);
        w = wx1 * wy0 * wz0; e = unpack_h2(q1.x); a0 = fmaf(w, e.x, a0); a1 = fmaf(w, e.y, a1);
        w = wx1 * wy0 * wz1; e = unpack_h2(q1.y); a0 = fmaf(w, e.x, a0); a1 = fmaf(w, e.y, a1);
        w = wx1 * wy1 * wz0; e = unpack_h2(q1.z); a0 = fmaf(w, e.x, a0); a1 = fmaf(w, e.y, a1);
        w = wx1 * wy1 * wz1; e = unpack_h2(q1.w); a0 = fmaf(w, e.x, a0); a1 = fmaf(w, e.y, a1);
    } else {
        // ---- hashed path on fp16 tables ----
        uint32_t hx0 = (uint32_t)cx;
        uint32_t hx1 = hx0 + 1u;
        uint32_t hy0 = (uint32_t)cy * P1;
        uint32_t hy1 = hy0 + P1;
        uint32_t hzb = (uint32_t)cz * P2;
        uint32_t hz0 = hzb        ^ (uint32_t)lvl;
        uint32_t hz1 = (hzb + P2) ^ (uint32_t)lvl;

        const uint32_t* __restrict__ tbl = g_htab + ((size_t)(lvl - 3) << 19);

        uint32_t hj[4];
        hj[0] = hy0 ^ hz0;
        hj[1] = hy0 ^ hz1;
        hj[2] = hy1 ^ hz0;
        hj[3] = hy1 ^ hz1;

        uint32_t t = hx0 ^ hx1;
        float2 e[8];

        if (t == 1u) {
            const uint2* __restrict__ tbl2 = (const uint2*)tbl;
#pragma unroll
            for (int j = 0; j < 4; ++j) {
                uint32_t i0 = (hx0 ^ hj[j]) & TABLE_MASK;
                uint2 q = __ldg(tbl2 + (i0 >> 1));
                uint32_t a = i0 & 1u;
                e[j]     = unpack_h2(a ? q.y : q.x);
                e[j + 4] = unpack_h2(a ? q.x : q.y);
            }
        } else if (t == 3u) {
            const uint4* __restrict__ tbl4 = (const uint4*)tbl;
#pragma unroll
            for (int j = 0; j < 4; ++j) {
                uint32_t i0 = (hx0 ^ hj[j]) & TABLE_MASK;
                uint4 q = __ldg(tbl4 + (i0 >> 2));
                uint32_t a = i0 & 3u;
                uint32_t ea = (a & 2u) ? ((a & 1u) ? q.w : q.z)
                                       : ((a & 1u) ? q.y : q.x);
                uint32_t eb = (a & 2u) ? ((a & 1u) ? q.x : q.y)
                                       : ((a & 1u) ? q.z : q.w);
                e[j]     = unpack_h2(ea);
                e[j + 4] = unpack_h2(eb);
            }
        } else {
#pragma unroll
            for (int j = 0; j < 4; ++j) {
                e[j]     = unpack_h2(__ldg(tbl + ((hx0 ^ hj[j]) & TABLE_MASK)));
                e[j + 4] = unpack_h2(__ldg(tbl + ((hx1 ^ hj[j]) & TABLE_MASK)));
            }
        }

        float w[8];
#pragma unroll
        for (int k = 0; k < 8; ++k) {
            w[k] = ((k & 4) ? wx1 : wx0)
                 * ((k & 2) ? wy1 : wy0)
                 * ((k & 1) ? wz1 : wz0);
        }
        a0 = 0.0f; a1 = 0.0f;
#pragma unroll
        for (int k = 0; k < 8; ++k) {
            a0 = fmaf(w[k], e[k].x, a0);
            a1 = fmaf(w[k], e[k].y, a1);
        }
    }

    s_stage[pt * 17 + lvl] = make_float2(a0 * FP16_INVSCALE, a1 * FP16_INVSCALE);
    __syncthreads();

    // coalesced flush: 16 points x 128B contiguous
    int g2 = blockIdx.x * 256 + tid;
    if (g2 < N * NUM_LEVELS) {
        ((float2*)out)[g2] = s_stage[(tid >> 4) * 17 + (tid & 15)];
    }
}

extern "C" void kernel_launch(void* const* d_in, const int* in_sizes, int n_in,
                              void* d_out, int out_size)
{
    const float* x      = (const float*)d_in[0];
    const float* tables = (const float*)d_in[1];
    float* out          = (float*)d_out;

    int N = in_sizes[0] / 3;
    int blocks = (N + 15) / 16;        // 16 points per block

    reset_kernel<<<1, 32>>>();
    fused_kernel<<<blocks, 256>>>(tables, x, out, N);
}